// round 8
// baseline (speedup 1.0000x reference)
#include <cuda_runtime.h>
#include <cuda_bf16.h>
#include <cstdint>

// ---------------- problem constants ----------------
#define SS    1024
#define INW   32
#define HH    128
#define NTHR  512          // 16 warps: (gate-group wg 0..7) x (k-half kh 0..1)
#define NBLK  128          // 4 batch rows per CTA
#define KTOT  160          // 128 h + 32 x
#define NKT   10           // k16 tiles total
#define KHT   5            // k16 tiles per k-half
#define BST   168          // B staging stride in bf16 (conflict-free)
#define BTERM (8 * BST * 2)        // 2688 B per term
#define GSTR  6            // gbuf stride in floats

#define OFF_ALO    0
#define ALO_BYTES  (512 * KTOT * 2)            // 163840: W_lo fragments, all 10 kt
#define OFF_AHI    ALO_BYTES                    // W_hi fragments for kt=4 (kh0) and kt=9 (kh1)
#define AHI_BYTES  (8 * 4 * 2 * 32 * 16)       // 32768
#define OFF_B      (OFF_AHI + AHI_BYTES)       // 196608
#define OFF_GBUF   (OFF_B + 2 * BTERM)         // 201984: float[2][512][GSTR]
#define GBUF_F     (2 * 512 * GSTR)
#define OFF_LRED   (OFF_GBUF + GBUF_F * 4)     // 226560
#define SMEM_BYTES (OFF_LRED + 256)            // 226816 <= 232448 cap

// ---------------- helpers ----------------
__device__ __forceinline__ unsigned short bf16_bits(float v) {
    __nv_bfloat16 b = __float2bfloat16(v);
    return *reinterpret_cast<unsigned short*>(&b);
}
__device__ __forceinline__ float bf16_val(unsigned short s) {
    __nv_bfloat16 b = *reinterpret_cast<__nv_bfloat16*>(&s);
    return __bfloat162float(b);
}
__device__ __forceinline__ void split_bf16(float w, unsigned short& hi, unsigned short& lo) {
    hi = bf16_bits(w);
    lo = bf16_bits(w - bf16_val(hi));
}
__device__ __forceinline__ uint32_t pack2(unsigned short a16, unsigned short b16) {
    return (uint32_t)a16 | ((uint32_t)b16 << 16);
}
__device__ __forceinline__ void mma_bf16(float& d0, float& d1, float& d2, float& d3,
                                         uint32_t a0, uint32_t a1, uint32_t a2, uint32_t a3,
                                         uint32_t b0, uint32_t b1) {
    asm volatile(
        "mma.sync.aligned.m16n8k16.row.col.f32.bf16.bf16.f32 "
        "{%0,%1,%2,%3}, {%4,%5,%6,%7}, {%8,%9}, {%0,%1,%2,%3};"
        : "+f"(d0), "+f"(d1), "+f"(d2), "+f"(d3)
        : "r"(a0), "r"(a1), "r"(a2), "r"(a3), "r"(b0), "r"(b1));
}
__device__ __forceinline__ float sigmoid_f(float v) {
    return __fdividef(1.0f, 1.0f + __expf(-v));
}
__device__ __forceinline__ float tanh_f(float v) {
    return 1.0f - __fdividef(2.0f, __expf(2.0f * v) + 1.0f);
}

__global__ void __launch_bounds__(NTHR, 1)
lstm_mma_kernel(const float* __restrict__ x,     // [B,S,IN]
                const float* __restrict__ Wih,   // [4H,IN]
                const float* __restrict__ Whh,   // [4H,H]
                const float* __restrict__ bih,   // [4H]
                const float* __restrict__ bhh,   // [4H]
                const float* __restrict__ Wlin,  // [1, S*H]
                const float* __restrict__ blin,  // [1]
                float* __restrict__ out)         // [B,1]
{
    extern __shared__ char smc[];
    float* smf = reinterpret_cast<float*>(smc);
    const int tid  = threadIdx.x;
    const int wid  = tid >> 5;
    const int lane = tid & 31;
    const int wg   = wid & 7;            // gate group: gates wg*64 .. wg*64+63
    const int kh   = wid >> 3;           // k-half: kt in [kh*5, kh*5+5)
    const int b0   = blockIdx.x * 4;

    // ---------------- prologue ----------------
    for (int i = tid; i < (2 * BTERM) / 4; i += NTHR)
        reinterpret_cast<uint32_t*>(smc + OFF_B)[i] = 0;
    for (int i = tid; i < GBUF_F; i += NTHR)
        smf[(OFF_GBUF >> 2) + i] = 0.0f;

    // Build W fragments. W_hi for q<4 -> registers; q==4 -> smem (AHI).
    // W_lo (all kt) -> smem (ALO) in fragment order.
    uint32_t wa[4][4][4];
    {
        const int r  = lane >> 2;
        const int kc = (lane & 3) * 2;
        #pragma unroll
        for (int mt = 0; mt < 4; mt++) {
            #pragma unroll
            for (int q = 0; q < KHT; q++) {
                const int kt = kh * KHT + q;
                uint32_t hi4[4], lo4[4];
                #pragma unroll
                for (int rg = 0; rg < 4; rg++) {
                    int g = wg * 64 + mt * 16 + r + ((rg & 1) ? 8 : 0);
                    int k = kt * 16 + kc + ((rg & 2) ? 8 : 0);
                    float2 w2;
                    if (k < HH) w2 = *reinterpret_cast<const float2*>(Whh + (size_t)g * HH + k);
                    else        w2 = *reinterpret_cast<const float2*>(Wih + (size_t)g * INW + (k - HH));
                    unsigned short h0, l0, h1, l1;
                    split_bf16(w2.x, h0, l0);
                    split_bf16(w2.y, h1, l1);
                    hi4[rg] = pack2(h0, h1);
                    lo4[rg] = pack2(l0, l1);
                }
                *reinterpret_cast<uint4*>(smc + OFF_ALO +
                    (size_t)((((wg * 4 + mt) * NKT + kt) * 32 + lane) * 16))
                    = make_uint4(lo4[0], lo4[1], lo4[2], lo4[3]);
                if (q < 4) {
                    wa[mt][q][0] = hi4[0]; wa[mt][q][1] = hi4[1];
                    wa[mt][q][2] = hi4[2]; wa[mt][q][3] = hi4[3];
                } else {
                    *reinterpret_cast<uint4*>(smc + OFF_AHI +
                        (size_t)((((wg * 4 + mt) * 2 + kh) * 32 + lane) * 16))
                        = make_uint4(hi4[0], hi4[1], hi4[2], hi4[3]);
                }
            }
        }
    }

    // ew role: thread owns unit j of batch row n
    const int j = tid >> 2;
    const int n = tid & 3;
    const float bI = bih[j]       + bhh[j];
    const float bF = bih[j + 128] + bhh[j + 128];
    const float bG = bih[j + 256] + bhh[j + 256];
    const float bO = bih[j + 384] + bhh[j + 384];
    float cst = 0.0f, lin = 0.0f;

    __syncthreads();                     // B staging zero complete
    if (tid < 64) {
        int row = tid >> 4, i0 = (tid & 15) * 2;
        float2 xv = *reinterpret_cast<const float2*>(
            x + ((size_t)(b0 + row) * SS + 0) * INW + i0);
        unsigned short h0, l0, h1, l1;
        split_bf16(xv.x, h0, l0);
        split_bf16(xv.y, h1, l1);
        char* p = smc + OFF_B + (size_t)(row * BST + HH + i0) * 2;
        *reinterpret_cast<uint32_t*>(p)         = pack2(h0, h1);
        *reinterpret_cast<uint32_t*>(p + BTERM) = pack2(l0, l1);
    }
    __syncthreads();

    const int bn = lane >> 2;
    const int bk = (lane & 3) * 2;

    // ---------------- main recurrence ----------------
    #pragma unroll 1
    for (int t = 0; t < SS; t++) {
        const float wl = __ldg(Wlin + (size_t)t * HH + j);
        float2 xv = make_float2(0.0f, 0.0f);
        if (tid < 64) {
            int row = tid >> 4, i0 = (tid & 15) * 2;
            int tn = (t + 1 < SS) ? (t + 1) : (SS - 1);
            xv = *reinterpret_cast<const float2*>(
                x + ((size_t)(b0 + row) * SS + tn) * INW + i0);
        }

        // === MMA phase: this warp's k-half of D = Whi*Bhi + Whi*Blo + Wlo*Bhi ===
        float d0[4], d1[4], d2[4], d3[4];
        #pragma unroll
        for (int mt = 0; mt < 4; mt++) { d0[mt] = 0.f; d1[mt] = 0.f; d2[mt] = 0.f; d3[mt] = 0.f; }

        #pragma unroll
        for (int q = 0; q < KHT; q++) {
            const int kt = kh * KHT + q;
            const char* bb = smc + OFF_B + (size_t)((bn * BST + kt * 16 + bk) * 2);
            uint32_t bh0 = *reinterpret_cast<const uint32_t*>(bb);
            uint32_t bh1 = *reinterpret_cast<const uint32_t*>(bb + 16);
            uint32_t bl0 = *reinterpret_cast<const uint32_t*>(bb + BTERM);
            uint32_t bl1 = *reinterpret_cast<const uint32_t*>(bb + BTERM + 16);
            #pragma unroll
            for (int mt = 0; mt < 4; mt++) {
                const uint4 alo = *reinterpret_cast<const uint4*>(smc + OFF_ALO +
                    (size_t)((((wg * 4 + mt) * NKT + kt) * 32 + lane) * 16));
                uint32_t a0, a1, a2, a3;
                if (q < 4) {
                    a0 = wa[mt][q][0]; a1 = wa[mt][q][1];
                    a2 = wa[mt][q][2]; a3 = wa[mt][q][3];
                } else {
                    const uint4 ahi = *reinterpret_cast<const uint4*>(smc + OFF_AHI +
                        (size_t)((((wg * 4 + mt) * 2 + kh) * 32 + lane) * 16));
                    a0 = ahi.x; a1 = ahi.y; a2 = ahi.z; a3 = ahi.w;
                }
                mma_bf16(d0[mt], d1[mt], d2[mt], d3[mt], a0, a1, a2, a3, bh0, bh1);
                mma_bf16(d0[mt], d1[mt], d2[mt], d3[mt], a0, a1, a2, a3, bl0, bl1);
                mma_bf16(d0[mt], d1[mt], d2[mt], d3[mt], alo.x, alo.y, alo.z, alo.w, bh0, bh1);
            }
        }
        // store partials to this k-half's gbuf (batch cols 0..3 in lanes lane%4<2)
        if ((lane & 2) == 0) {
            const int c = (lane & 3) * 2;
            const int r = lane >> 2;
            float* gbase = smf + (OFF_GBUF >> 2) + kh * (512 * GSTR);
            #pragma unroll
            for (int mt = 0; mt < 4; mt++) {
                int gm = wg * 64 + mt * 16 + r;
                *reinterpret_cast<float2*>(gbase + gm * GSTR + c)
                    = make_float2(d0[mt], d1[mt]);
                *reinterpret_cast<float2*>(gbase + (gm + 8) * GSTR + c)
                    = make_float2(d2[mt], d3[mt]);
            }
        }
        __syncthreads();

        // === elementwise: unit j of row n; sum the two k-half partials ===
        {
            const float* g0 = smf + (OFF_GBUF >> 2) + n;
            const float* g1 = g0 + 512 * GSTR;
            float pi = g0[(j)       * GSTR] + g1[(j)       * GSTR] + bI;
            float pf = g0[(j + 128) * GSTR] + g1[(j + 128) * GSTR] + bF;
            float pg = g0[(j + 256) * GSTR] + g1[(j + 256) * GSTR] + bG;
            float po = g0[(j + 384) * GSTR] + g1[(j + 384) * GSTR] + bO;

            float iv = sigmoid_f(pi);
            float fv = sigmoid_f(pf);
            float gv = tanh_f(pg);
            float ov = sigmoid_f(po);
            cst = fmaf(fv, cst, iv * gv);
            float hv = ov * tanh_f(cst);
            lin = fmaf(hv, wl, lin);

            unsigned short h16, l16;
            split_bf16(hv, h16, l16);
            char* p = smc + OFF_B + (size_t)(n * BST + j) * 2;
            *reinterpret_cast<unsigned short*>(p)         = h16;
            *reinterpret_cast<unsigned short*>(p + BTERM) = l16;
        }
        if (tid < 64) {
            int row = tid >> 4, i0 = (tid & 15) * 2;
            unsigned short h0, l0, h1, l1;
            split_bf16(xv.x, h0, l0);
            split_bf16(xv.y, h1, l1);
            char* p = smc + OFF_B + (size_t)(row * BST + HH + i0) * 2;
            *reinterpret_cast<uint32_t*>(p)         = pack2(h0, h1);
            *reinterpret_cast<uint32_t*>(p + BTERM) = pack2(l0, l1);
        }
        __syncthreads();
    }

    // ---------------- epilogue ----------------
    // lin held per (j, n); reduce over j within warp (n preserved by xor>=4)
    float v = lin;
    #pragma unroll
    for (int off = 4; off <= 16; off <<= 1) v += __shfl_xor_sync(0xffffffffu, v, off);
    if (lane < 4) smf[(OFF_LRED >> 2) + wid * 4 + lane] = v;   // lane == n
    __syncthreads();
    if (tid < 4) {
        float s = blin[0];
        #pragma unroll
        for (int w = 0; w < 16; w++) s += smf[(OFF_LRED >> 2) + w * 4 + tid];
        out[b0 + tid] = s;
    }
}

extern "C" void kernel_launch(void* const* d_in, const int* in_sizes, int n_in,
                              void* d_out, int out_size)
{
    const float* x    = (const float*)d_in[0];
    const float* Wih  = (const float*)d_in[1];
    const float* Whh  = (const float*)d_in[2];
    const float* bih  = (const float*)d_in[3];
    const float* bhh  = (const float*)d_in[4];
    const float* Wlin = (const float*)d_in[5];
    const float* blin = (const float*)d_in[6];
    float* out = (float*)d_out;

    cudaFuncSetAttribute(lstm_mma_kernel,
                         cudaFuncAttributeMaxDynamicSharedMemorySize, SMEM_BYTES);
    lstm_mma_kernel<<<NBLK, NTHR, SMEM_BYTES>>>(x, Wih, Whh, bih, bhh, Wlin, blin, out);
}

// round 9
// speedup vs baseline: 1.0961x; 1.0961x over previous
#include <cuda_runtime.h>
#include <cuda_bf16.h>
#include <cstdint>

// ---------------- problem constants ----------------
#define SS    1024
#define INW   32
#define HH    128
#define NTHR  512          // 16 warps; warp w owns gates w*32 .. w*32+31 (2 m-tiles, full K)
#define NBLK  128          // 4 batch rows per CTA
#define KTOT  160          // 128 h + 32 x
#define NKT   10           // k16 tiles
#define BST   168          // B staging stride in bf16 (conflict-free)
#define BTERM (8 * BST * 2)        // 2688 B per term
#define GSTR  6            // gbuf stride in floats

#define OFF_ALO    0
#define ALO_BYTES  (512 * KTOT * 2)            // 163840: W_lo fragments (16w x 2mt x 10kt x 32 x 16B)
#define OFF_B      ALO_BYTES                    // 163840
#define OFF_GBUF   (OFF_B + 2 * BTERM)         // 169216: float[512][GSTR]
#define OFF_LRED   (OFF_GBUF + 512 * GSTR * 4) // 181504
#define SMEM_BYTES (OFF_LRED + 256)            // 181760

// ---------------- helpers ----------------
__device__ __forceinline__ unsigned short bf16_bits(float v) {
    __nv_bfloat16 b = __float2bfloat16(v);
    return *reinterpret_cast<unsigned short*>(&b);
}
__device__ __forceinline__ float bf16_val(unsigned short s) {
    __nv_bfloat16 b = *reinterpret_cast<__nv_bfloat16*>(&s);
    return __bfloat162float(b);
}
__device__ __forceinline__ void split_bf16(float w, unsigned short& hi, unsigned short& lo) {
    hi = bf16_bits(w);
    lo = bf16_bits(w - bf16_val(hi));
}
__device__ __forceinline__ uint32_t pack2(unsigned short a16, unsigned short b16) {
    return (uint32_t)a16 | ((uint32_t)b16 << 16);
}
__device__ __forceinline__ void mma_bf16(float& d0, float& d1, float& d2, float& d3,
                                         uint32_t a0, uint32_t a1, uint32_t a2, uint32_t a3,
                                         uint32_t b0, uint32_t b1) {
    asm volatile(
        "mma.sync.aligned.m16n8k16.row.col.f32.bf16.bf16.f32 "
        "{%0,%1,%2,%3}, {%4,%5,%6,%7}, {%8,%9}, {%0,%1,%2,%3};"
        : "+f"(d0), "+f"(d1), "+f"(d2), "+f"(d3)
        : "r"(a0), "r"(a1), "r"(a2), "r"(a3), "r"(b0), "r"(b1));
}
__device__ __forceinline__ float sigmoid_f(float v) {
    return __fdividef(1.0f, 1.0f + __expf(-v));
}
__device__ __forceinline__ float tanh_f(float v) {
    return 1.0f - __fdividef(2.0f, __expf(2.0f * v) + 1.0f);
}

__global__ void __launch_bounds__(NTHR, 1)
lstm_mma_kernel(const float* __restrict__ x,     // [B,S,IN]
                const float* __restrict__ Wih,   // [4H,IN]
                const float* __restrict__ Whh,   // [4H,H]
                const float* __restrict__ bih,   // [4H]
                const float* __restrict__ bhh,   // [4H]
                const float* __restrict__ Wlin,  // [1, S*H]
                const float* __restrict__ blin,  // [1]
                float* __restrict__ out)         // [B,1]
{
    extern __shared__ char smc[];
    float* smf = reinterpret_cast<float*>(smc);
    const int tid  = threadIdx.x;
    const int wid  = tid >> 5;
    const int lane = tid & 31;
    const int b0   = blockIdx.x * 4;

    // ---------------- prologue ----------------
    for (int i = tid; i < (2 * BTERM) / 4; i += NTHR)
        reinterpret_cast<uint32_t*>(smc + OFF_B)[i] = 0;
    for (int i = tid; i < 512 * GSTR; i += NTHR)
        smf[(OFF_GBUF >> 2) + i] = 0.0f;

    // W fragments: hi -> registers (2 mt x 10 kt x 4 = 80 regs); lo -> smem.
    uint32_t wa[2][NKT][4];
    {
        const int r  = lane >> 2;
        const int kc = (lane & 3) * 2;
        #pragma unroll
        for (int mt = 0; mt < 2; mt++) {
            #pragma unroll
            for (int kt = 0; kt < NKT; kt++) {
                uint32_t lo4[4];
                #pragma unroll
                for (int rg = 0; rg < 4; rg++) {
                    int g = wid * 32 + mt * 16 + r + ((rg & 1) ? 8 : 0);
                    int k = kt * 16 + kc + ((rg & 2) ? 8 : 0);
                    float2 w2;
                    if (k < HH) w2 = *reinterpret_cast<const float2*>(Whh + (size_t)g * HH + k);
                    else        w2 = *reinterpret_cast<const float2*>(Wih + (size_t)g * INW + (k - HH));
                    unsigned short h0, l0, h1, l1;
                    split_bf16(w2.x, h0, l0);
                    split_bf16(w2.y, h1, l1);
                    wa[mt][kt][rg] = pack2(h0, h1);
                    lo4[rg]        = pack2(l0, l1);
                }
                *reinterpret_cast<uint4*>(smc + OFF_ALO +
                    (size_t)((((wid * 2 + mt) * NKT + kt) * 32 + lane) * 16))
                    = make_uint4(lo4[0], lo4[1], lo4[2], lo4[3]);
            }
        }
    }

    // ew role: thread owns unit j of batch row n
    const int j = tid >> 2;
    const int n = tid & 3;
    const float bI = bih[j]       + bhh[j];
    const float bF = bih[j + 128] + bhh[j + 128];
    const float bG = bih[j + 256] + bhh[j + 256];
    const float bO = bih[j + 384] + bhh[j + 384];
    float cst = 0.0f, lin = 0.0f;

    __syncthreads();                     // B staging zero complete
    if (tid < 64) {
        int row = tid >> 4, i0 = (tid & 15) * 2;
        float2 xv = *reinterpret_cast<const float2*>(
            x + ((size_t)(b0 + row) * SS + 0) * INW + i0);
        unsigned short h0, l0, h1, l1;
        split_bf16(xv.x, h0, l0);
        split_bf16(xv.y, h1, l1);
        char* p = smc + OFF_B + (size_t)(row * BST + HH + i0) * 2;
        *reinterpret_cast<uint32_t*>(p)         = pack2(h0, h1);
        *reinterpret_cast<uint32_t*>(p + BTERM) = pack2(l0, l1);
    }
    __syncthreads();

    const int bn = lane >> 2;
    const int bk = (lane & 3) * 2;

    // ---------------- main recurrence ----------------
    #pragma unroll 1
    for (int t = 0; t < SS; t++) {
        const float wl = __ldg(Wlin + (size_t)t * HH + j);
        float2 xv = make_float2(0.0f, 0.0f);
        if (tid < 64) {
            int row = tid >> 4, i0 = (tid & 15) * 2;
            int tn = (t + 1 < SS) ? (t + 1) : (SS - 1);
            xv = *reinterpret_cast<const float2*>(
                x + ((size_t)(b0 + row) * SS + tn) * INW + i0);
        }

        // === MMA phase: 2 m-tiles x full K, 3 terms ===
        float d0[2], d1[2], d2[2], d3[2];
        #pragma unroll
        for (int mt = 0; mt < 2; mt++) { d0[mt] = 0.f; d1[mt] = 0.f; d2[mt] = 0.f; d3[mt] = 0.f; }

        #pragma unroll
        for (int kt = 0; kt < NKT; kt++) {
            const char* bb = smc + OFF_B + (size_t)((bn * BST + kt * 16 + bk) * 2);
            uint32_t bh0 = *reinterpret_cast<const uint32_t*>(bb);
            uint32_t bh1 = *reinterpret_cast<const uint32_t*>(bb + 16);
            uint32_t bl0 = *reinterpret_cast<const uint32_t*>(bb + BTERM);
            uint32_t bl1 = *reinterpret_cast<const uint32_t*>(bb + BTERM + 16);
            const uint4 alo0 = *reinterpret_cast<const uint4*>(smc + OFF_ALO +
                (size_t)((((wid * 2 + 0) * NKT + kt) * 32 + lane) * 16));
            const uint4 alo1 = *reinterpret_cast<const uint4*>(smc + OFF_ALO +
                (size_t)((((wid * 2 + 1) * NKT + kt) * 32 + lane) * 16));
            // interleave accumulator chains mt0/mt1 (reuse distance 2)
            mma_bf16(d0[0], d1[0], d2[0], d3[0],
                     wa[0][kt][0], wa[0][kt][1], wa[0][kt][2], wa[0][kt][3], bh0, bh1);
            mma_bf16(d0[1], d1[1], d2[1], d3[1],
                     wa[1][kt][0], wa[1][kt][1], wa[1][kt][2], wa[1][kt][3], bh0, bh1);
            mma_bf16(d0[0], d1[0], d2[0], d3[0],
                     wa[0][kt][0], wa[0][kt][1], wa[0][kt][2], wa[0][kt][3], bl0, bl1);
            mma_bf16(d0[1], d1[1], d2[1], d3[1],
                     wa[1][kt][0], wa[1][kt][1], wa[1][kt][2], wa[1][kt][3], bl0, bl1);
            mma_bf16(d0[0], d1[0], d2[0], d3[0],
                     alo0.x, alo0.y, alo0.z, alo0.w, bh0, bh1);
            mma_bf16(d0[1], d1[1], d2[1], d3[1],
                     alo1.x, alo1.y, alo1.z, alo1.w, bh0, bh1);
        }
        // store D (batch cols 0..3 live in lanes with lane%4 < 2)
        if ((lane & 2) == 0) {
            const int c = (lane & 3) * 2;
            const int r = lane >> 2;
            #pragma unroll
            for (int mt = 0; mt < 2; mt++) {
                int gm = wid * 32 + mt * 16 + r;
                *reinterpret_cast<float2*>(smf + (OFF_GBUF >> 2) + gm * GSTR + c)
                    = make_float2(d0[mt], d1[mt]);
                *reinterpret_cast<float2*>(smf + (OFF_GBUF >> 2) + (gm + 8) * GSTR + c)
                    = make_float2(d2[mt], d3[mt]);
            }
        }
        __syncthreads();

        // === elementwise: unit j of row n ===
        {
            const float* gb = smf + (OFF_GBUF >> 2) + n;
            float pi = gb[(j)       * GSTR] + bI;
            float pf = gb[(j + 128) * GSTR] + bF;
            float pg = gb[(j + 256) * GSTR] + bG;
            float po = gb[(j + 384) * GSTR] + bO;

            float iv = sigmoid_f(pi);
            float fv = sigmoid_f(pf);
            float gv = tanh_f(pg);
            float ov = sigmoid_f(po);
            cst = fmaf(fv, cst, iv * gv);
            float hv = ov * tanh_f(cst);
            lin = fmaf(hv, wl, lin);

            unsigned short h16, l16;
            split_bf16(hv, h16, l16);
            char* p = smc + OFF_B + (size_t)(n * BST + j) * 2;
            *reinterpret_cast<unsigned short*>(p)         = h16;
            *reinterpret_cast<unsigned short*>(p + BTERM) = l16;
        }
        if (tid < 64) {
            int row = tid >> 4, i0 = (tid & 15) * 2;
            unsigned short h0, l0, h1, l1;
            split_bf16(xv.x, h0, l0);
            split_bf16(xv.y, h1, l1);
            char* p = smc + OFF_B + (size_t)(row * BST + HH + i0) * 2;
            *reinterpret_cast<uint32_t*>(p)         = pack2(h0, h1);
            *reinterpret_cast<uint32_t*>(p + BTERM) = pack2(l0, l1);
        }
        __syncthreads();
    }

    // ---------------- epilogue ----------------
    // lin held per (j, n); reduce over j within warp (n preserved by xor>=4)
    float v = lin;
    #pragma unroll
    for (int off = 4; off <= 16; off <<= 1) v += __shfl_xor_sync(0xffffffffu, v, off);
    if (lane < 4) smf[(OFF_LRED >> 2) + wid * 4 + lane] = v;   // lane == n
    __syncthreads();
    if (tid < 4) {
        float s = blin[0];
        #pragma unroll
        for (int w = 0; w < 16; w++) s += smf[(OFF_LRED >> 2) + w * 4 + tid];
        out[b0 + tid] = s;
    }
}

extern "C" void kernel_launch(void* const* d_in, const int* in_sizes, int n_in,
                              void* d_out, int out_size)
{
    const float* x    = (const float*)d_in[0];
    const float* Wih  = (const float*)d_in[1];
    const float* Whh  = (const float*)d_in[2];
    const float* bih  = (const float*)d_in[3];
    const float* bhh  = (const float*)d_in[4];
    const float* Wlin = (const float*)d_in[5];
    const float* blin = (const float*)d_in[6];
    float* out = (float*)d_out;

    cudaFuncSetAttribute(lstm_mma_kernel,
                         cudaFuncAttributeMaxDynamicSharedMemorySize, SMEM_BYTES);
    lstm_mma_kernel<<<NBLK, NTHR, SMEM_BYTES>>>(x, Wih, Whh, bih, bhh, Wlin, blin, out);
}

// round 10
// speedup vs baseline: 1.1123x; 1.0148x over previous
#include <cuda_runtime.h>
#include <cuda_bf16.h>
#include <cstdint>

// ---------------- problem constants ----------------
#define SS    1024
#define INW   32
#define HH    128
#define NTHR  256          // 8 warps; warp w owns gates w*64 .. w*64+63 (4 m-tiles, full K)
#define NBLK  128          // 4 batch rows per CTA
#define KTOT  160          // 128 h + 32 x
#define NKT   10           // k16 tiles
#define NKR   8            // k16 tiles with W_hi in registers
#define BST   168          // B staging stride in bf16 (conflict-free)
#define BTERM (8 * BST * 2)        // 2688 B per term
#define GSTR  6            // gbuf stride in floats

#define OFF_ALO    0
#define ALO_BYTES  (512 * KTOT * 2)            // 163840: W_lo fragments (8w x 4mt x 10kt)
#define OFF_AHI    ALO_BYTES                    // W_hi fragments for kt = 8,9
#define AHI_BYTES  (8 * 4 * 2 * 32 * 16)       // 32768
#define OFF_B      (OFF_AHI + AHI_BYTES)       // 196608
#define OFF_GBUF   (OFF_B + 2 * BTERM)         // 201984: float[512][GSTR]
#define OFF_LRED   (OFF_GBUF + 512 * GSTR * 4) // 214272
#define SMEM_BYTES (OFF_LRED + 256)            // 214528 < cap

// ---------------- helpers ----------------
__device__ __forceinline__ unsigned short bf16_bits(float v) {
    __nv_bfloat16 b = __float2bfloat16(v);
    return *reinterpret_cast<unsigned short*>(&b);
}
__device__ __forceinline__ float bf16_val(unsigned short s) {
    __nv_bfloat16 b = *reinterpret_cast<__nv_bfloat16*>(&s);
    return __bfloat162float(b);
}
__device__ __forceinline__ void split_bf16(float w, unsigned short& hi, unsigned short& lo) {
    hi = bf16_bits(w);
    lo = bf16_bits(w - bf16_val(hi));
}
__device__ __forceinline__ uint32_t pack2(unsigned short a16, unsigned short b16) {
    return (uint32_t)a16 | ((uint32_t)b16 << 16);
}
__device__ __forceinline__ void mma_bf16(float& d0, float& d1, float& d2, float& d3,
                                         uint32_t a0, uint32_t a1, uint32_t a2, uint32_t a3,
                                         uint32_t b0, uint32_t b1) {
    asm volatile(
        "mma.sync.aligned.m16n8k16.row.col.f32.bf16.bf16.f32 "
        "{%0,%1,%2,%3}, {%4,%5,%6,%7}, {%8,%9}, {%0,%1,%2,%3};"
        : "+f"(d0), "+f"(d1), "+f"(d2), "+f"(d3)
        : "r"(a0), "r"(a1), "r"(a2), "r"(a3), "r"(b0), "r"(b1));
}
__device__ __forceinline__ float sigmoid_f(float v) {
    return __fdividef(1.0f, 1.0f + __expf(-v));
}
__device__ __forceinline__ float tanh_f(float v) {
    return 1.0f - __fdividef(2.0f, __expf(2.0f * v) + 1.0f);
}

__global__ void __launch_bounds__(NTHR, 1)
lstm_mma_kernel(const float* __restrict__ x,     // [B,S,IN]
                const float* __restrict__ Wih,   // [4H,IN]
                const float* __restrict__ Whh,   // [4H,H]
                const float* __restrict__ bih,   // [4H]
                const float* __restrict__ bhh,   // [4H]
                const float* __restrict__ Wlin,  // [1, S*H]
                const float* __restrict__ blin,  // [1]
                float* __restrict__ out)         // [B,1]
{
    extern __shared__ char smc[];
    float* smf = reinterpret_cast<float*>(smc);
    const int tid  = threadIdx.x;
    const int wid  = tid >> 5;
    const int lane = tid & 31;
    const int b0   = blockIdx.x * 4;

    // ---------------- prologue ----------------
    for (int i = tid; i < (2 * BTERM) / 4; i += NTHR)
        reinterpret_cast<uint32_t*>(smc + OFF_B)[i] = 0;
    for (int i = tid; i < 512 * GSTR; i += NTHR)
        smf[(OFF_GBUF >> 2) + i] = 0.0f;
    if (tid < 64) smf[(OFF_LRED >> 2) + tid] = 0.0f;

    // W fragments: hi kt 0..7 -> registers (128 regs); hi kt 8,9 -> smem AHI;
    // lo (all kt) -> smem ALO in fragment order.
    uint32_t wa[4][NKR][4];
    {
        const int r  = lane >> 2;
        const int kc = (lane & 3) * 2;
        #pragma unroll
        for (int mt = 0; mt < 4; mt++) {
            #pragma unroll
            for (int kt = 0; kt < NKT; kt++) {
                uint32_t hi4[4], lo4[4];
                #pragma unroll
                for (int rg = 0; rg < 4; rg++) {
                    int g = wid * 64 + mt * 16 + r + ((rg & 1) ? 8 : 0);
                    int k = kt * 16 + kc + ((rg & 2) ? 8 : 0);
                    float2 w2;
                    if (k < HH) w2 = *reinterpret_cast<const float2*>(Whh + (size_t)g * HH + k);
                    else        w2 = *reinterpret_cast<const float2*>(Wih + (size_t)g * INW + (k - HH));
                    unsigned short h0, l0, h1, l1;
                    split_bf16(w2.x, h0, l0);
                    split_bf16(w2.y, h1, l1);
                    hi4[rg] = pack2(h0, h1);
                    lo4[rg] = pack2(l0, l1);
                }
                *reinterpret_cast<uint4*>(smc + OFF_ALO +
                    (size_t)((((wid * 4 + mt) * NKT + kt) * 32 + lane) * 16))
                    = make_uint4(lo4[0], lo4[1], lo4[2], lo4[3]);
                if (kt < NKR) {
                    wa[mt][kt][0] = hi4[0]; wa[mt][kt][1] = hi4[1];
                    wa[mt][kt][2] = hi4[2]; wa[mt][kt][3] = hi4[3];
                } else {
                    *reinterpret_cast<uint4*>(smc + OFF_AHI +
                        (size_t)((((wid * 4 + mt) * 2 + (kt - NKR)) * 32 + lane) * 16))
                        = make_uint4(hi4[0], hi4[1], hi4[2], hi4[3]);
                }
            }
        }
    }

    // ew role: thread owns units (j0, j0+1) of batch row n
    const int j0 = (tid >> 2) * 2;
    const int n  = tid & 3;
    const float bi0 = bih[j0]           + bhh[j0];
    const float bi1 = bih[j0 + 1]       + bhh[j0 + 1];
    const float bf0 = bih[j0 + 128]     + bhh[j0 + 128];
    const float bf1 = bih[j0 + 129]     + bhh[j0 + 129];
    const float bg0 = bih[j0 + 256]     + bhh[j0 + 256];
    const float bg1 = bih[j0 + 257]     + bhh[j0 + 257];
    const float bo0 = bih[j0 + 384]     + bhh[j0 + 384];
    const float bo1 = bih[j0 + 385]     + bhh[j0 + 385];
    float c0 = 0.0f, c1 = 0.0f;
    float lin = 0.0f;

    __syncthreads();                       // B staging zero complete
    if (tid < 64) {
        int row = tid >> 4, i0 = (tid & 15) * 2;
        float2 xv = *reinterpret_cast<const float2*>(
            x + ((size_t)(b0 + row) * SS + 0) * INW + i0);
        unsigned short h0, l0, h1, l1;
        split_bf16(xv.x, h0, l0);
        split_bf16(xv.y, h1, l1);
        char* p = smc + OFF_B + (size_t)(row * BST + HH + i0) * 2;
        *reinterpret_cast<uint32_t*>(p)         = pack2(h0, h1);
        *reinterpret_cast<uint32_t*>(p + BTERM) = pack2(l0, l1);
    }
    __syncthreads();

    const int bn = lane >> 2;
    const int bk = (lane & 3) * 2;

    // ---------------- main recurrence ----------------
    #pragma unroll 1
    for (int t = 0; t < SS; t++) {
        const float2 wl2 = __ldg(reinterpret_cast<const float2*>(
            Wlin + (size_t)t * HH + j0));
        float2 xv = make_float2(0.0f, 0.0f);
        if (tid < 64) {
            int row = tid >> 4, i0 = (tid & 15) * 2;
            int tn = (t + 1 < SS) ? (t + 1) : (SS - 1);
            xv = *reinterpret_cast<const float2*>(
                x + ((size_t)(b0 + row) * SS + tn) * INW + i0);
        }

        // === MMA phase: term-major inner order (same-acc reuse distance 4) ===
        float d0[4], d1[4], d2[4], d3[4];
        #pragma unroll
        for (int mt = 0; mt < 4; mt++) { d0[mt] = 0.f; d1[mt] = 0.f; d2[mt] = 0.f; d3[mt] = 0.f; }

        #pragma unroll
        for (int kt = 0; kt < NKT; kt++) {
            const char* bb = smc + OFF_B + (size_t)((bn * BST + kt * 16 + bk) * 2);
            uint32_t bh0 = *reinterpret_cast<const uint32_t*>(bb);
            uint32_t bh1 = *reinterpret_cast<const uint32_t*>(bb + 16);
            uint32_t bl0 = *reinterpret_cast<const uint32_t*>(bb + BTERM);
            uint32_t bl1 = *reinterpret_cast<const uint32_t*>(bb + BTERM + 16);

            uint32_t ah[4][4];
            if (kt < NKR) {
                #pragma unroll
                for (int mt = 0; mt < 4; mt++) {
                    ah[mt][0] = wa[mt][kt][0]; ah[mt][1] = wa[mt][kt][1];
                    ah[mt][2] = wa[mt][kt][2]; ah[mt][3] = wa[mt][kt][3];
                }
            } else {
                #pragma unroll
                for (int mt = 0; mt < 4; mt++) {
                    const uint4 v = *reinterpret_cast<const uint4*>(smc + OFF_AHI +
                        (size_t)((((wid * 4 + mt) * 2 + (kt - NKR)) * 32 + lane) * 16));
                    ah[mt][0] = v.x; ah[mt][1] = v.y; ah[mt][2] = v.z; ah[mt][3] = v.w;
                }
            }
            uint4 alo[4];
            #pragma unroll
            for (int mt = 0; mt < 4; mt++)
                alo[mt] = *reinterpret_cast<const uint4*>(smc + OFF_ALO +
                    (size_t)((((wid * 4 + mt) * NKT + kt) * 32 + lane) * 16));

            // term 1: hi * b_hi  (mt 0..3)
            #pragma unroll
            for (int mt = 0; mt < 4; mt++)
                mma_bf16(d0[mt], d1[mt], d2[mt], d3[mt],
                         ah[mt][0], ah[mt][1], ah[mt][2], ah[mt][3], bh0, bh1);
            // term 2: hi * b_lo  (mt 0..3)
            #pragma unroll
            for (int mt = 0; mt < 4; mt++)
                mma_bf16(d0[mt], d1[mt], d2[mt], d3[mt],
                         ah[mt][0], ah[mt][1], ah[mt][2], ah[mt][3], bl0, bl1);
            // term 3: lo * b_hi  (mt 0..3)
            #pragma unroll
            for (int mt = 0; mt < 4; mt++)
                mma_bf16(d0[mt], d1[mt], d2[mt], d3[mt],
                         alo[mt].x, alo[mt].y, alo[mt].z, alo[mt].w, bh0, bh1);
        }
        // store D (batch cols 0..3 live in lanes with lane%4 < 2)
        if ((lane & 2) == 0) {
            const int c = (lane & 3) * 2;
            const int r = lane >> 2;
            #pragma unroll
            for (int mt = 0; mt < 4; mt++) {
                int gm = wid * 64 + mt * 16 + r;
                *reinterpret_cast<float2*>(smf + (OFF_GBUF >> 2) + gm * GSTR + c)
                    = make_float2(d0[mt], d1[mt]);
                *reinterpret_cast<float2*>(smf + (OFF_GBUF >> 2) + (gm + 8) * GSTR + c)
                    = make_float2(d2[mt], d3[mt]);
            }
        }
        __syncthreads();

        // === elementwise: units j0, j0+1 of row n ===
        {
            const float* gb = smf + (OFF_GBUF >> 2) + n;
            float pi0 = gb[(j0)       * GSTR] + bi0;
            float pi1 = gb[(j0 + 1)   * GSTR] + bi1;
            float pf0 = gb[(j0 + 128) * GSTR] + bf0;
            float pf1 = gb[(j0 + 129) * GSTR] + bf1;
            float pg0 = gb[(j0 + 256) * GSTR] + bg0;
            float pg1 = gb[(j0 + 257) * GSTR] + bg1;
            float po0 = gb[(j0 + 384) * GSTR] + bo0;
            float po1 = gb[(j0 + 385) * GSTR] + bo1;

            float iv0 = sigmoid_f(pi0), iv1 = sigmoid_f(pi1);
            float fv0 = sigmoid_f(pf0), fv1 = sigmoid_f(pf1);
            float gv0 = tanh_f(pg0),    gv1 = tanh_f(pg1);
            float ov0 = sigmoid_f(po0), ov1 = sigmoid_f(po1);
            c0 = fmaf(fv0, c0, iv0 * gv0);
            c1 = fmaf(fv1, c1, iv1 * gv1);
            float hv0 = ov0 * tanh_f(c0);
            float hv1 = ov1 * tanh_f(c1);
            lin = fmaf(hv0, wl2.x, fmaf(hv1, wl2.y, lin));

            unsigned short h0, l0, h1, l1;
            split_bf16(hv0, h0, l0);
            split_bf16(hv1, h1, l1);
            char* p = smc + OFF_B + (size_t)(n * BST + j0) * 2;
            *reinterpret_cast<uint32_t*>(p)         = pack2(h0, h1);
            *reinterpret_cast<uint32_t*>(p + BTERM) = pack2(l0, l1);
        }
        if (tid < 64) {
            int row = tid >> 4, i0 = (tid & 15) * 2;
            unsigned short h0, l0, h1, l1;
            split_bf16(xv.x, h0, l0);
            split_bf16(xv.y, h1, l1);
            char* p = smc + OFF_B + (size_t)(row * BST + HH + i0) * 2;
            *reinterpret_cast<uint32_t*>(p)         = pack2(h0, h1);
            *reinterpret_cast<uint32_t*>(p + BTERM) = pack2(l0, l1);
        }
        __syncthreads();
    }

    // ---------------- epilogue ----------------
    float v = lin;
    #pragma unroll
    for (int off = 4; off <= 16; off <<= 1) v += __shfl_xor_sync(0xffffffffu, v, off);
    if (lane < 4) smf[(OFF_LRED >> 2) + wid * 4 + lane] = v;   // lane == n
    __syncthreads();
    if (tid < 4) {
        float s = blin[0];
        #pragma unroll
        for (int w = 0; w < 8; w++) s += smf[(OFF_LRED >> 2) + w * 4 + tid];
        out[b0 + tid] = s;
    }
}

extern "C" void kernel_launch(void* const* d_in, const int* in_sizes, int n_in,
                              void* d_out, int out_size)
{
    const float* x    = (const float*)d_in[0];
    const float* Wih  = (const float*)d_in[1];
    const float* Whh  = (const float*)d_in[2];
    const float* bih  = (const float*)d_in[3];
    const float* bhh  = (const float*)d_in[4];
    const float* Wlin = (const float*)d_in[5];
    const float* blin = (const float*)d_in[6];
    float* out = (float*)d_out;

    cudaFuncSetAttribute(lstm_mma_kernel,
                         cudaFuncAttributeMaxDynamicSharedMemorySize, SMEM_BYTES);
    lstm_mma_kernel<<<NBLK, NTHR, SMEM_BYTES>>>(x, Wih, Whh, bih, bhh, Wlin, blin, out);
}